// round 4
// baseline (speedup 1.0000x reference)
#include <cuda_runtime.h>
#include <math.h>
#include <stdint.h>

#define D    128
#define D4   512
#define MAXN 100000
#define MAXE 1000000

// ---------------- scratch (no allocations allowed) ----------------
__device__ float g_H  [MAXN * D];    // gelu(LN1(x)), later LN2(conv)
__device__ float g_HW [MAXN * D];    // h @ W_conv
__device__ float g_F1 [MAXN * D4];   // FFN hidden
__device__ int   g_deg [MAXN];       // in-degree (edges only)
__device__ int   g_off [MAXN + 1];   // CSR offsets
__device__ int   g_pos [MAXN];       // fill cursors
__device__ int   g_csr [MAXE];       // src per edge, grouped by dst
__device__ float g_dinv[MAXN];
__device__ int   g_eflag;            // 1 => edge_index stored as int32

__device__ __forceinline__ float gelu_f(float x) {
    return 0.5f * x * (1.0f + erff(x * 0.70710678118654752f));
}

__device__ __forceinline__ uint32_t tf32_bits(float x) {
    uint32_t r;
    asm("cvt.rna.tf32.f32 %0, %1;" : "=r"(r) : "f"(x));
    return r;
}

// ---------------- edge dtype detection ----------------
__global__ void k_detect(const unsigned long long* __restrict__ p, long long E,
                         unsigned long long N) {
    __shared__ int bad;
    if (threadIdx.x == 0) bad = 0;
    __syncthreads();
    long long step = E / (long long)blockDim.x;
    if (step < 1) step = 1;
    long long idx = (long long)threadIdx.x * step;
    if (idx < E && p[idx] >= N) bad = 1;
    __syncthreads();
    if (threadIdx.x == 0) g_eflag = bad;
}

// ---------------- row LayerNorm (LN1 + gelu) ----------------
__global__ void k_rowln1(const float* __restrict__ x,
                         const float* __restrict__ g, const float* __restrict__ b,
                         float* __restrict__ out, int N) {
    int row = blockIdx.x * blockDim.y + threadIdx.y;
    if (row >= N) return;
    int l = threadIdx.x;
    float4 v = ((const float4*)(x + (size_t)row * D))[l];
    float s  = v.x + v.y + v.z + v.w;
    float ss = v.x*v.x + v.y*v.y + v.z*v.z + v.w*v.w;
    #pragma unroll
    for (int o = 16; o; o >>= 1) {
        s  += __shfl_xor_sync(0xffffffffu, s,  o);
        ss += __shfl_xor_sync(0xffffffffu, ss, o);
    }
    float mu  = s * (1.0f / D);
    float var = ss * (1.0f / D) - mu * mu;
    float rs  = rsqrtf(var + 1e-5f);
    float4 gg = ((const float4*)g)[l];
    float4 bb = ((const float4*)b)[l];
    float4 r;
    r.x = gelu_f((v.x - mu) * rs * gg.x + bb.x);
    r.y = gelu_f((v.y - mu) * rs * gg.y + bb.y);
    r.z = gelu_f((v.z - mu) * rs * gg.z + bb.z);
    r.w = gelu_f((v.w - mu) * rs * gg.w + bb.w);
    ((float4*)(out + (size_t)row * D))[l] = r;
}

// ---------------- degree histogram ----------------
__global__ void k_deginit(int N) {
    int i = blockIdx.x * blockDim.x + threadIdx.x;
    if (i < N) g_deg[i] = 0;
}
__global__ void k_degcount(const void* __restrict__ ei, int E) {
    int e = blockIdx.x * blockDim.x + threadIdx.x;
    if (e >= E) return;
    int dst;
    if (g_eflag) dst = ((const int*)ei)[E + e];
    else         dst = (int)((const long long*)ei)[E + e];
    atomicAdd(&g_deg[dst], 1);
}

// ---------------- single-block scan: offsets, cursors, dinv ----------------
__global__ void k_scan(int N, int E) {
    __shared__ int part[1024];
    int tid = threadIdx.x;
    int chunk = (N + 1023) / 1024;
    int lo = tid * chunk, hi = lo + chunk;
    if (hi > N) hi = N;
    int s = 0;
    for (int i = lo; i < hi; i++) s += g_deg[i];
    part[tid] = s;
    __syncthreads();
    for (int off = 1; off < 1024; off <<= 1) {
        int t = (tid >= off) ? part[tid - off] : 0;
        __syncthreads();
        part[tid] += t;
        __syncthreads();
    }
    int run = part[tid] - s;   // exclusive base for this chunk
    for (int i = lo; i < hi; i++) {
        g_off[i] = run;
        g_pos[i] = run;
        int d = g_deg[i];
        run += d;
        g_dinv[i] = rsqrtf((float)(d + 1));   // +1 self loop
    }
    if (tid == 0) g_off[N] = E;
}

// ---------------- CSR fill ----------------
__global__ void k_fill(const void* __restrict__ ei, int E) {
    int e = blockIdx.x * blockDim.x + threadIdx.x;
    if (e >= E) return;
    int s, d2;
    if (g_eflag) { const int* p = (const int*)ei; s = p[e]; d2 = p[E + e]; }
    else { const long long* p = (const long long*)ei; s = (int)p[e]; d2 = (int)p[E + e]; }
    int pos = atomicAdd(&g_pos[d2], 1);
    g_csr[pos] = s;
}

// ---------------- gather aggregation fused with LN2 ----------------
// One warp per dst row. agg = dinv[d] * (hW[d]*dinv[d] + sum_src hW[src]*dinv[src]).
// Then H = LN2(x + agg + b_conv).
__global__ void k_gather_ln2(const float* __restrict__ x,
                             const float* __restrict__ bconv,
                             const float* __restrict__ g, const float* __restrict__ b,
                             float* __restrict__ out, int N) {
    int row = blockIdx.x * (blockDim.x >> 5) + (threadIdx.x >> 5);
    if (row >= N) return;
    int lane = threadIdx.x & 31;
    float di = g_dinv[row];
    float4 acc = ((const float4*)g_HW)[row * 32 + lane];
    acc.x *= di; acc.y *= di; acc.z *= di; acc.w *= di;
    int e0 = g_off[row], e1 = g_off[row + 1];
    for (int e = e0; e < e1; e++) {
        int s = g_csr[e];                 // broadcast load across the warp
        float c = g_dinv[s];
        float4 v = ((const float4*)g_HW)[s * 32 + lane];
        acc.x = fmaf(v.x, c, acc.x);
        acc.y = fmaf(v.y, c, acc.y);
        acc.z = fmaf(v.z, c, acc.z);
        acc.w = fmaf(v.w, c, acc.w);
    }
    float4 xv  = ((const float4*)x)[row * 32 + lane];
    float4 bcv = ((const float4*)bconv)[lane];
    float4 v;
    v.x = xv.x + acc.x * di + bcv.x;
    v.y = xv.y + acc.y * di + bcv.y;
    v.z = xv.z + acc.z * di + bcv.z;
    v.w = xv.w + acc.w * di + bcv.w;
    float s  = v.x + v.y + v.z + v.w;
    float ss = v.x*v.x + v.y*v.y + v.z*v.z + v.w*v.w;
    #pragma unroll
    for (int o = 16; o; o >>= 1) {
        s  += __shfl_xor_sync(0xffffffffu, s,  o);
        ss += __shfl_xor_sync(0xffffffffu, ss, o);
    }
    float mu  = s * (1.0f / D);
    float var = ss * (1.0f / D) - mu * mu;
    float rs  = rsqrtf(var + 1e-5f);
    float4 gg = ((const float4*)g)[lane];
    float4 bb = ((const float4*)b)[lane];
    float4 r;
    r.x = (v.x - mu) * rs * gg.x + bb.x;
    r.y = (v.y - mu) * rs * gg.y + bb.y;
    r.z = (v.z - mu) * rs * gg.z + bb.z;
    r.w = (v.w - mu) * rs * gg.w + bb.w;
    ((float4*)(out + (size_t)row * D))[lane] = r;
}

// ---------------- tf32 mma.sync GEMM --------------------------------------
#define KCH 64
#define APITCH 68
#define WPITCH 136

__global__ void __launch_bounds__(256, 1) k_gemm_tc(
    const float* __restrict__ A, const float* __restrict__ W,
    const float* __restrict__ bias, const float* __restrict__ res,
    float* __restrict__ out, int N, int K, int ncols, int mode)
{
    extern __shared__ float sm[];
    float* As = sm;                    // [128][APITCH]
    float* Ws = sm + 128 * APITCH;     // [KCH][WPITCH]

    int tid = threadIdx.x, wid = tid >> 5, lane = tid & 31;
    int rowBase = blockIdx.x * 128, colBase = blockIdx.y * 128;
    int wm = (wid & 3) * 32;
    int wn = (wid >> 2) * 64;
    int lq = lane >> 2, lr = lane & 3;

    float acc[2][8][4];
    #pragma unroll
    for (int i = 0; i < 2; i++)
        #pragma unroll
        for (int j = 0; j < 8; j++)
            #pragma unroll
            for (int k = 0; k < 4; k++) acc[i][j][k] = 0.0f;

    for (int kc = 0; kc < K; kc += KCH) {
        for (int idx = tid; idx < 128 * (KCH / 4); idx += 256) {
            int r = idx >> 4, k4 = (idx & 15) << 2;
            float4 v = make_float4(0.f, 0.f, 0.f, 0.f);
            int gr = rowBase + r;
            if (gr < N) v = *(const float4*)&A[(size_t)gr * K + kc + k4];
            uint4 t;
            t.x = tf32_bits(v.x); t.y = tf32_bits(v.y);
            t.z = tf32_bits(v.z); t.w = tf32_bits(v.w);
            *(uint4*)&As[r * APITCH + k4] = t;
        }
        for (int idx = tid; idx < KCH * 32; idx += 256) {
            int r = idx >> 5, n4 = (idx & 31) << 2;
            float4 v = *(const float4*)&W[(size_t)(kc + r) * ncols + colBase + n4];
            uint4 t;
            t.x = tf32_bits(v.x); t.y = tf32_bits(v.y);
            t.z = tf32_bits(v.z); t.w = tf32_bits(v.w);
            *(uint4*)&Ws[r * WPITCH + n4] = t;
        }
        __syncthreads();

        #pragma unroll
        for (int ks = 0; ks < KCH; ks += 8) {
            uint32_t a[2][4], b[8][2];
            #pragma unroll
            for (int mf = 0; mf < 2; mf++) {
                int r0 = wm + mf * 16 + lq;
                a[mf][0] = __float_as_uint(As[r0 * APITCH + ks + lr]);
                a[mf][1] = __float_as_uint(As[(r0 + 8) * APITCH + ks + lr]);
                a[mf][2] = __float_as_uint(As[r0 * APITCH + ks + lr + 4]);
                a[mf][3] = __float_as_uint(As[(r0 + 8) * APITCH + ks + lr + 4]);
            }
            #pragma unroll
            for (int nf = 0; nf < 8; nf++) {
                int c0 = wn + nf * 8 + lq;
                b[nf][0] = __float_as_uint(Ws[(ks + lr) * WPITCH + c0]);
                b[nf][1] = __float_as_uint(Ws[(ks + lr + 4) * WPITCH + c0]);
            }
            #pragma unroll
            for (int mf = 0; mf < 2; mf++)
                #pragma unroll
                for (int nf = 0; nf < 8; nf++) {
                    asm volatile(
                        "mma.sync.aligned.m16n8k8.row.col.f32.tf32.tf32.f32 "
                        "{%0,%1,%2,%3}, {%4,%5,%6,%7}, {%8,%9}, {%0,%1,%2,%3};"
                        : "+f"(acc[mf][nf][0]), "+f"(acc[mf][nf][1]),
                          "+f"(acc[mf][nf][2]), "+f"(acc[mf][nf][3])
                        : "r"(a[mf][0]), "r"(a[mf][1]), "r"(a[mf][2]), "r"(a[mf][3]),
                          "r"(b[nf][0]), "r"(b[nf][1]));
                }
        }
        __syncthreads();
    }

    #pragma unroll
    for (int mf = 0; mf < 2; mf++) {
        int r0 = rowBase + wm + mf * 16 + lq;
        #pragma unroll
        for (int half = 0; half < 2; half++) {
            int row = r0 + half * 8;
            if (row >= N) continue;
            #pragma unroll
            for (int nf = 0; nf < 8; nf++) {
                int col = colBase + wn + nf * 8 + lr * 2;
                float v0 = acc[mf][nf][half * 2];
                float v1 = acc[mf][nf][half * 2 + 1];
                if (mode >= 1) {
                    v0 = gelu_f(v0 + bias[col]);
                    v1 = gelu_f(v1 + bias[col + 1]);
                }
                if (mode == 2) {
                    float2 r2 = *(const float2*)&res[(size_t)row * ncols + col];
                    v0 += r2.x; v1 += r2.y;
                }
                *(float2*)&out[(size_t)row * ncols + col] = make_float2(v0, v1);
            }
        }
    }
}

// ---------------- launch ----------------
extern "C" void kernel_launch(void* const* d_in, const int* in_sizes, int n_in,
                              void* d_out, int out_size) {
    const float* x    = (const float*)d_in[0];
    const void*  ei   = d_in[1];
    const float* ln1g = (const float*)d_in[3];
    const float* ln1b = (const float*)d_in[4];
    const float* Wc   = (const float*)d_in[5];
    const float* bc   = (const float*)d_in[6];
    const float* ln2g = (const float*)d_in[7];
    const float* ln2b = (const float*)d_in[8];
    const float* W1   = (const float*)d_in[9];
    const float* b1   = (const float*)d_in[10];
    const float* W2   = (const float*)d_in[11];
    const float* b2   = (const float*)d_in[12];
    float* out = (float*)d_out;

    int N = in_sizes[0] / D;
    int E = in_sizes[1] / 2;

    const int gemm_smem = (128 * APITCH + KCH * WPITCH) * (int)sizeof(float);
    static int attr_set = 0;
    if (!attr_set) {
        cudaFuncSetAttribute(k_gemm_tc, cudaFuncAttributeMaxDynamicSharedMemorySize, gemm_smem);
        attr_set = 1;
    }

    float* gH;   cudaGetSymbolAddress((void**)&gH,   g_H);
    float* gHW;  cudaGetSymbolAddress((void**)&gHW,  g_HW);
    float* gF1;  cudaGetSymbolAddress((void**)&gF1,  g_F1);

    dim3 lnBlk(32, 8);
    int lnGrid = (N + 7) / 8;
    int rowBlocks = (N + 127) / 128;

    // 0. edge dtype detection
    k_detect<<<1, 256>>>((const unsigned long long*)ei, (long long)E,
                         (unsigned long long)N);
    // 1. H = gelu(LN1(x))
    k_rowln1<<<lnGrid, lnBlk>>>(x, ln1g, ln1b, gH, N);
    // 2. HW = H @ W_conv
    k_gemm_tc<<<dim3(rowBlocks, 1), 256, gemm_smem>>>(
        gH, Wc, nullptr, nullptr, gHW, N, D, D, 0);
    // 3-6. CSR build: histogram -> scan -> fill
    k_deginit<<<(N + 255) / 256, 256>>>(N);
    k_degcount<<<(E + 255) / 256, 256>>>(ei, E);
    k_scan<<<1, 1024>>>(N, E);
    k_fill<<<(E + 255) / 256, 256>>>(ei, E);
    // 7. H = LN2(x + agg + b_conv)  [gather, fused]
    {
        int wpb = 8;  // 8 warps = 8 rows per block
        int blocks = (N + wpb - 1) / wpb;
        k_gather_ln2<<<blocks, wpb * 32>>>(x, bc, ln2g, ln2b, gH, N);
    }
    // 8. F1 = gelu(H @ W1 + b1)
    k_gemm_tc<<<dim3(rowBlocks, 4), 256, gemm_smem>>>(
        gH, W1, b1, nullptr, gF1, N, D, D4, 1);
    // 9. out = x + gelu(F1 @ W2 + b2)
    k_gemm_tc<<<dim3(rowBlocks, 1), 256, gemm_smem>>>(
        gF1, W2, b2, x, out, N, D4, D, 2);
}

// round 5
// speedup vs baseline: 1.1725x; 1.1725x over previous
#include <cuda_runtime.h>
#include <math.h>
#include <stdint.h>

#define D    128
#define D4   512
#define MAXN 100000
#define MAXE 1000000

// ---------------- scratch (no allocations allowed) ----------------
__device__ float g_H  [MAXN * D];    // gelu(LN1(x)), later LN2(conv)
__device__ float g_HW [MAXN * D];    // (h @ W_conv) * dinv[row]   (pre-scaled)
__device__ float g_F1 [MAXN * D4];   // FFN hidden
__device__ int   g_deg [MAXN];
__device__ int   g_off [MAXN + 1];
__device__ int   g_pos [MAXN];
__device__ int   g_csr [MAXE];
__device__ float g_dinv[MAXN];
__device__ int   g_eflag;            // 1 => edge_index stored as int32

__device__ __forceinline__ float gelu_f(float x) {
    return 0.5f * x * (1.0f + erff(x * 0.70710678118654752f));
}
__device__ __forceinline__ uint32_t tf32_bits(float x) {
    uint32_t r;
    asm("cvt.rna.tf32.f32 %0, %1;" : "=r"(r) : "f"(x));
    return r;
}

// ---------------- edge dtype detection ----------------
__global__ void k_detect(const unsigned long long* __restrict__ p, long long E,
                         unsigned long long N) {
    __shared__ int bad;
    if (threadIdx.x == 0) bad = 0;
    __syncthreads();
    long long step = E / (long long)blockDim.x;
    if (step < 1) step = 1;
    long long idx = (long long)threadIdx.x * step;
    if (idx < E && p[idx] >= N) bad = 1;
    __syncthreads();
    if (threadIdx.x == 0) g_eflag = bad;
}

// ---------------- LN1 + gelu ----------------
__global__ void k_rowln1(const float* __restrict__ x,
                         const float* __restrict__ g, const float* __restrict__ b,
                         float* __restrict__ out, int N) {
    int row = blockIdx.x * blockDim.y + threadIdx.y;
    if (row >= N) return;
    int l = threadIdx.x;
    float4 v = ((const float4*)(x + (size_t)row * D))[l];
    float s  = v.x + v.y + v.z + v.w;
    float ss = v.x*v.x + v.y*v.y + v.z*v.z + v.w*v.w;
    #pragma unroll
    for (int o = 16; o; o >>= 1) {
        s  += __shfl_xor_sync(0xffffffffu, s,  o);
        ss += __shfl_xor_sync(0xffffffffu, ss, o);
    }
    float mu  = s * (1.0f / D);
    float var = ss * (1.0f / D) - mu * mu;
    float rs  = rsqrtf(var + 1e-5f);
    float4 gg = ((const float4*)g)[l];
    float4 bb = ((const float4*)b)[l];
    float4 r;
    r.x = gelu_f((v.x - mu) * rs * gg.x + bb.x);
    r.y = gelu_f((v.y - mu) * rs * gg.y + bb.y);
    r.z = gelu_f((v.z - mu) * rs * gg.z + bb.z);
    r.w = gelu_f((v.w - mu) * rs * gg.w + bb.w);
    ((float4*)(out + (size_t)row * D))[l] = r;
}

// ---------------- degree histogram / scan / CSR fill ----------------
__global__ void k_deginit(int N) {
    int i = blockIdx.x * blockDim.x + threadIdx.x;
    if (i < N) g_deg[i] = 0;
}
__global__ void k_degcount(const void* __restrict__ ei, int E) {
    int e = blockIdx.x * blockDim.x + threadIdx.x;
    if (e >= E) return;
    int dst;
    if (g_eflag) dst = ((const int*)ei)[E + e];
    else         dst = (int)((const long long*)ei)[E + e];
    atomicAdd(&g_deg[dst], 1);
}
__global__ void k_scan(int N, int E) {
    __shared__ int part[1024];
    int tid = threadIdx.x;
    int chunk = (N + 1023) / 1024;
    int lo = tid * chunk, hi = lo + chunk;
    if (hi > N) hi = N;
    int s = 0;
    for (int i = lo; i < hi; i++) s += g_deg[i];
    part[tid] = s;
    __syncthreads();
    for (int off = 1; off < 1024; off <<= 1) {
        int t = (tid >= off) ? part[tid - off] : 0;
        __syncthreads();
        part[tid] += t;
        __syncthreads();
    }
    int run = part[tid] - s;
    for (int i = lo; i < hi; i++) {
        g_off[i] = run;
        g_pos[i] = run;
        int d = g_deg[i];
        run += d;
        g_dinv[i] = rsqrtf((float)(d + 1));
    }
    if (tid == 0) g_off[N] = E;
}
__global__ void k_fill(const void* __restrict__ ei, int E) {
    int e = blockIdx.x * blockDim.x + threadIdx.x;
    if (e >= E) return;
    int s, d2;
    if (g_eflag) { const int* p = (const int*)ei; s = p[e]; d2 = p[E + e]; }
    else { const long long* p = (const long long*)ei; s = (int)p[e]; d2 = (int)p[E + e]; }
    int pos = atomicAdd(&g_pos[d2], 1);
    g_csr[pos] = s;
}

// ---------------- gather (MLP=4) fused with LN2 ----------------
// g_HW holds pre-scaled rows hWs[i] = hW[i]*dinv[i].
// agg[d] = dinv[d] * (hWs[d] + sum_src hWs[src]);  H = LN2(x + agg + b_conv)
__global__ void k_gather_ln2(const float* __restrict__ x,
                             const float* __restrict__ bconv,
                             const float* __restrict__ g, const float* __restrict__ b,
                             float* __restrict__ out, int N) {
    int row = blockIdx.x * (blockDim.x >> 5) + (threadIdx.x >> 5);
    if (row >= N) return;
    int lane = threadIdx.x & 31;
    float4 acc = ((const float4*)g_HW)[row * 32 + lane];   // self term (scaled)
    int e = g_off[row], e1 = g_off[row + 1];
    for (; e + 4 <= e1; e += 4) {
        int s0 = g_csr[e], s1 = g_csr[e + 1], s2 = g_csr[e + 2], s3 = g_csr[e + 3];
        float4 v0 = ((const float4*)g_HW)[s0 * 32 + lane];
        float4 v1 = ((const float4*)g_HW)[s1 * 32 + lane];
        float4 v2 = ((const float4*)g_HW)[s2 * 32 + lane];
        float4 v3 = ((const float4*)g_HW)[s3 * 32 + lane];
        acc.x += (v0.x + v1.x) + (v2.x + v3.x);
        acc.y += (v0.y + v1.y) + (v2.y + v3.y);
        acc.z += (v0.z + v1.z) + (v2.z + v3.z);
        acc.w += (v0.w + v1.w) + (v2.w + v3.w);
    }
    for (; e < e1; e++) {
        int s = g_csr[e];
        float4 v = ((const float4*)g_HW)[s * 32 + lane];
        acc.x += v.x; acc.y += v.y; acc.z += v.z; acc.w += v.w;
    }
    float di = g_dinv[row];
    float4 xv  = ((const float4*)x)[row * 32 + lane];
    float4 bcv = ((const float4*)bconv)[lane];
    float4 v;
    v.x = xv.x + acc.x * di + bcv.x;
    v.y = xv.y + acc.y * di + bcv.y;
    v.z = xv.z + acc.z * di + bcv.z;
    v.w = xv.w + acc.w * di + bcv.w;
    float s  = v.x + v.y + v.z + v.w;
    float ss = v.x*v.x + v.y*v.y + v.z*v.z + v.w*v.w;
    #pragma unroll
    for (int o = 16; o; o >>= 1) {
        s  += __shfl_xor_sync(0xffffffffu, s,  o);
        ss += __shfl_xor_sync(0xffffffffu, ss, o);
    }
    float mu  = s * (1.0f / D);
    float var = ss * (1.0f / D) - mu * mu;
    float rs  = rsqrtf(var + 1e-5f);
    float4 gg = ((const float4*)g)[lane];
    float4 bb = ((const float4*)b)[lane];
    float4 r;
    r.x = (v.x - mu) * rs * gg.x + bb.x;
    r.y = (v.y - mu) * rs * gg.y + bb.y;
    r.z = (v.z - mu) * rs * gg.z + bb.z;
    r.w = (v.w - mu) * rs * gg.w + bb.w;
    ((float4*)(out + (size_t)row * D))[lane] = r;
}

// ---------------- tf32 mma.sync GEMM, double-buffered staging -------------
// CTA 256 thr -> 128x128 tile; warps 4(m)x2(n), warp tile 32x64; KCH=64.
// mode 0: raw. 1: gelu(acc+bias). 2: res + gelu(acc+bias). 3: acc*dinv[row].
#define KCH 64
#define APITCH 68
#define WPITCH 136
#define ABUF (128 * APITCH)
#define WBUF (KCH * WPITCH)
#define GEMM_SMEM ((2 * (ABUF + WBUF)) * (int)sizeof(float))

__global__ void __launch_bounds__(256, 1) k_gemm_tc(
    const float* __restrict__ A, const float* __restrict__ W,
    const float* __restrict__ bias, const float* __restrict__ res,
    const float* __restrict__ dinv,
    float* __restrict__ out, int N, int K, int ncols, int mode)
{
    extern __shared__ float sm[];
    // layout: As0, As1, Ws0, Ws1
    int tid = threadIdx.x, wid = tid >> 5, lane = tid & 31;
    int rowBase = blockIdx.x * 128, colBase = blockIdx.y * 128;
    int wm = (wid & 3) * 32;
    int wn = (wid >> 2) * 64;
    int lq = lane >> 2, lr = lane & 3;

    float4 aR[8], wR[8];
    int aRow[8];

    // decompositions (shared by load & store):
    // A: idx in [0,2048): r = idx>>4, k4 = (idx&15)<<2
    // W: idx in [0,2048): rr = idx>>5, n4 = (idx&31)<<2
    #pragma unroll
    for (int i = 0; i < 8; i++) aRow[i] = rowBase + ((tid + i * 256) >> 4);

    auto load_regs = [&](int kc) {
        #pragma unroll
        for (int i = 0; i < 8; i++) {
            int idx = tid + i * 256;
            int k4 = (idx & 15) << 2;
            aR[i] = (aRow[i] < N)
                  ? *(const float4*)&A[(size_t)aRow[i] * K + kc + k4]
                  : make_float4(0.f, 0.f, 0.f, 0.f);
        }
        #pragma unroll
        for (int i = 0; i < 8; i++) {
            int idx = tid + i * 256;
            int rr = idx >> 5, n4 = (idx & 31) << 2;
            wR[i] = *(const float4*)&W[(size_t)(kc + rr) * ncols + colBase + n4];
        }
    };
    auto store_smem = [&](int buf) {
        float* As = sm + buf * ABUF;
        float* Ws = sm + 2 * ABUF + buf * WBUF;
        #pragma unroll
        for (int i = 0; i < 8; i++) {
            int idx = tid + i * 256;
            int r = idx >> 4, k4 = (idx & 15) << 2;
            uint4 t;
            t.x = tf32_bits(aR[i].x); t.y = tf32_bits(aR[i].y);
            t.z = tf32_bits(aR[i].z); t.w = tf32_bits(aR[i].w);
            *(uint4*)&As[r * APITCH + k4] = t;
        }
        #pragma unroll
        for (int i = 0; i < 8; i++) {
            int idx = tid + i * 256;
            int rr = idx >> 5, n4 = (idx & 31) << 2;
            uint4 t;
            t.x = tf32_bits(wR[i].x); t.y = tf32_bits(wR[i].y);
            t.z = tf32_bits(wR[i].z); t.w = tf32_bits(wR[i].w);
            *(uint4*)&Ws[rr * WPITCH + n4] = t;
        }
    };

    float acc[2][8][4];
    #pragma unroll
    for (int i = 0; i < 2; i++)
        #pragma unroll
        for (int j = 0; j < 8; j++)
            #pragma unroll
            for (int k = 0; k < 4; k++) acc[i][j][k] = 0.0f;

    int nch = K / KCH;
    load_regs(0);
    store_smem(0);
    for (int ch = 0; ch < nch; ch++) {
        __syncthreads();                       // buf[ch&1] ready for all
        if (ch + 1 < nch) load_regs((ch + 1) * KCH);   // LDGs fly over MMA
        const float* As = sm + (ch & 1) * ABUF;
        const float* Ws = sm + 2 * ABUF + (ch & 1) * WBUF;
        #pragma unroll
        for (int ks = 0; ks < KCH; ks += 8) {
            uint32_t a[2][4], b[8][2];
            #pragma unroll
            for (int mf = 0; mf < 2; mf++) {
                int r0 = wm + mf * 16 + lq;
                a[mf][0] = __float_as_uint(As[r0 * APITCH + ks + lr]);
                a[mf][1] = __float_as_uint(As[(r0 + 8) * APITCH + ks + lr]);
                a[mf][2] = __float_as_uint(As[r0 * APITCH + ks + lr + 4]);
                a[mf][3] = __float_as_uint(As[(r0 + 8) * APITCH + ks + lr + 4]);
            }
            #pragma unroll
            for (int nf = 0; nf < 8; nf++) {
                int c0 = wn + nf * 8 + lq;
                b[nf][0] = __float_as_uint(Ws[(ks + lr) * WPITCH + c0]);
                b[nf][1] = __float_as_uint(Ws[(ks + lr + 4) * WPITCH + c0]);
            }
            #pragma unroll
            for (int mf = 0; mf < 2; mf++)
                #pragma unroll
                for (int nf = 0; nf < 8; nf++) {
                    asm volatile(
                        "mma.sync.aligned.m16n8k8.row.col.f32.tf32.tf32.f32 "
                        "{%0,%1,%2,%3}, {%4,%5,%6,%7}, {%8,%9}, {%0,%1,%2,%3};"
                        : "+f"(acc[mf][nf][0]), "+f"(acc[mf][nf][1]),
                          "+f"(acc[mf][nf][2]), "+f"(acc[mf][nf][3])
                        : "r"(a[mf][0]), "r"(a[mf][1]), "r"(a[mf][2]), "r"(a[mf][3]),
                          "r"(b[nf][0]), "r"(b[nf][1]));
                }
        }
        if (ch + 1 < nch) store_smem((ch + 1) & 1);   // safe: other buffer
    }

    #pragma unroll
    for (int mf = 0; mf < 2; mf++) {
        int r0 = rowBase + wm + mf * 16 + lq;
        #pragma unroll
        for (int half = 0; half < 2; half++) {
            int row = r0 + half * 8;
            if (row >= N) continue;
            float di = (mode == 3) ? dinv[row] : 1.0f;
            #pragma unroll
            for (int nf = 0; nf < 8; nf++) {
                int col = colBase + wn + nf * 8 + lr * 2;
                float v0 = acc[mf][nf][half * 2];
                float v1 = acc[mf][nf][half * 2 + 1];
                if (mode == 1 || mode == 2) {
                    v0 = gelu_f(v0 + bias[col]);
                    v1 = gelu_f(v1 + bias[col + 1]);
                }
                if (mode == 2) {
                    float2 r2 = *(const float2*)&res[(size_t)row * ncols + col];
                    v0 += r2.x; v1 += r2.y;
                }
                if (mode == 3) { v0 *= di; v1 *= di; }
                *(float2*)&out[(size_t)row * ncols + col] = make_float2(v0, v1);
            }
        }
    }
}

// ---------------- launch ----------------
extern "C" void kernel_launch(void* const* d_in, const int* in_sizes, int n_in,
                              void* d_out, int out_size) {
    const float* x    = (const float*)d_in[0];
    const void*  ei   = d_in[1];
    const float* ln1g = (const float*)d_in[3];
    const float* ln1b = (const float*)d_in[4];
    const float* Wc   = (const float*)d_in[5];
    const float* bc   = (const float*)d_in[6];
    const float* ln2g = (const float*)d_in[7];
    const float* ln2b = (const float*)d_in[8];
    const float* W1   = (const float*)d_in[9];
    const float* b1   = (const float*)d_in[10];
    const float* W2   = (const float*)d_in[11];
    const float* b2   = (const float*)d_in[12];
    float* out = (float*)d_out;

    int N = in_sizes[0] / D;
    int E = in_sizes[1] / 2;

    static int attr_set = 0;
    if (!attr_set) {
        cudaFuncSetAttribute(k_gemm_tc, cudaFuncAttributeMaxDynamicSharedMemorySize, GEMM_SMEM);
        attr_set = 1;
    }

    float* gH;    cudaGetSymbolAddress((void**)&gH,    g_H);
    float* gHW;   cudaGetSymbolAddress((void**)&gHW,   g_HW);
    float* gF1;   cudaGetSymbolAddress((void**)&gF1,   g_F1);
    float* gdinv; cudaGetSymbolAddress((void**)&gdinv, g_dinv);

    dim3 lnBlk(32, 8);
    int lnGrid = (N + 7) / 8;
    int rowBlocks = (N + 127) / 128;

    // 0. edge dtype detection
    k_detect<<<1, 256>>>((const unsigned long long*)ei, (long long)E,
                         (unsigned long long)N);
    // 1-4. CSR build (before GEMM1 so dinv is ready for its epilogue)
    k_deginit<<<(N + 255) / 256, 256>>>(N);
    k_degcount<<<(E + 255) / 256, 256>>>(ei, E);
    k_scan<<<1, 1024>>>(N, E);
    k_fill<<<(E + 255) / 256, 256>>>(ei, E);
    // 5. H = gelu(LN1(x))
    k_rowln1<<<lnGrid, lnBlk>>>(x, ln1g, ln1b, gH, N);
    // 6. HWs = (H @ W_conv) * dinv[row]
    k_gemm_tc<<<dim3(rowBlocks, 1), 256, GEMM_SMEM>>>(
        gH, Wc, nullptr, nullptr, gdinv, gHW, N, D, D, 3);
    // 7. H = LN2(x + agg + b_conv)   [gather, MLP=4]
    {
        int wpb = 8;
        int blocks = (N + wpb - 1) / wpb;
        k_gather_ln2<<<blocks, wpb * 32>>>(x, bc, ln2g, ln2b, gH, N);
    }
    // 8. F1 = gelu(H @ W1 + b1)
    k_gemm_tc<<<dim3(rowBlocks, 4), 256, GEMM_SMEM>>>(
        gH, W1, b1, nullptr, nullptr, gF1, N, D, D4, 1);
    // 9. out = x + gelu(F1 @ W2 + b2)
    k_gemm_tc<<<dim3(rowBlocks, 1), 256, GEMM_SMEM>>>(
        gF1, W2, b2, x, nullptr, out, N, D4, D, 2);
}

// round 6
// speedup vs baseline: 1.6642x; 1.4194x over previous
#include <cuda_runtime.h>
#include <math.h>
#include <stdint.h>

#define D    128
#define D4   512
#define MAXN 100000
#define MAXE 1000000

// ---------------- scratch (no allocations allowed) ----------------
__device__ float g_H  [MAXN * D];    // gelu(LN1(x)), later LN2(conv)
__device__ float g_HW [MAXN * D];    // (h @ W_conv) * dinv[row]   (pre-scaled)
__device__ float g_F1 [MAXN * D4];   // FFN hidden
__device__ int   g_deg [MAXN];
__device__ int   g_scanI[MAXN];      // block-local inclusive scan
__device__ int   g_bsum[128];        // per-block totals -> inclusive scan
__device__ int   g_off [MAXN + 1];
__device__ int   g_pos [MAXN];
__device__ int   g_csr [MAXE];
__device__ float g_dinv[MAXN];
__device__ int   g_eflag;            // 1 => edge_index stored as int32

__device__ __forceinline__ float gelu_f(float x) {
    return 0.5f * x * (1.0f + erff(x * 0.70710678118654752f));
}
__device__ __forceinline__ uint32_t tf32_bits(float x) {
    uint32_t r;
    asm("cvt.rna.tf32.f32 %0, %1;" : "=r"(r) : "f"(x));
    return r;
}

// ---------------- edge dtype detection ----------------
__global__ void k_detect(const unsigned long long* __restrict__ p, long long E,
                         unsigned long long N) {
    __shared__ int bad;
    if (threadIdx.x == 0) bad = 0;
    __syncthreads();
    long long step = E / (long long)blockDim.x;
    if (step < 1) step = 1;
    long long idx = (long long)threadIdx.x * step;
    if (idx < E && p[idx] >= N) bad = 1;
    __syncthreads();
    if (threadIdx.x == 0) g_eflag = bad;
}

// ---------------- LN1 + gelu ----------------
__global__ void k_rowln1(const float* __restrict__ x,
                         const float* __restrict__ g, const float* __restrict__ b,
                         float* __restrict__ out, int N) {
    int row = blockIdx.x * blockDim.y + threadIdx.y;
    if (row >= N) return;
    int l = threadIdx.x;
    float4 v = ((const float4*)(x + (size_t)row * D))[l];
    float s  = v.x + v.y + v.z + v.w;
    float ss = v.x*v.x + v.y*v.y + v.z*v.z + v.w*v.w;
    #pragma unroll
    for (int o = 16; o; o >>= 1) {
        s  += __shfl_xor_sync(0xffffffffu, s,  o);
        ss += __shfl_xor_sync(0xffffffffu, ss, o);
    }
    float mu  = s * (1.0f / D);
    float var = ss * (1.0f / D) - mu * mu;
    float rs  = rsqrtf(var + 1e-5f);
    float4 gg = ((const float4*)g)[l];
    float4 bb = ((const float4*)b)[l];
    float4 r;
    r.x = gelu_f((v.x - mu) * rs * gg.x + bb.x);
    r.y = gelu_f((v.y - mu) * rs * gg.y + bb.y);
    r.z = gelu_f((v.z - mu) * rs * gg.z + bb.z);
    r.w = gelu_f((v.w - mu) * rs * gg.w + bb.w);
    ((float4*)(out + (size_t)row * D))[l] = r;
}

// ---------------- degree histogram ----------------
__global__ void k_deginit(int N) {
    int i = blockIdx.x * blockDim.x + threadIdx.x;
    if (i < N) g_deg[i] = 0;
}
__global__ void k_degcount(const void* __restrict__ ei, int E) {
    int e = blockIdx.x * blockDim.x + threadIdx.x;
    if (e >= E) return;
    int dst;
    if (g_eflag) dst = ((const int*)ei)[E + e];
    else         dst = (int)((const long long*)ei)[E + e];
    atomicAdd(&g_deg[dst], 1);
}

// ---------------- parallel 3-phase scan ----------------
__global__ void k_scan1(int N) {
    __shared__ int sm[1024];
    int i = blockIdx.x * 1024 + threadIdx.x;
    int v = (i < N) ? g_deg[i] : 0;
    sm[threadIdx.x] = v;
    __syncthreads();
    #pragma unroll
    for (int off = 1; off < 1024; off <<= 1) {
        int t = (threadIdx.x >= off) ? sm[threadIdx.x - off] : 0;
        __syncthreads();
        sm[threadIdx.x] += t;
        __syncthreads();
    }
    if (i < N) g_scanI[i] = sm[threadIdx.x];
    if (threadIdx.x == 1023) g_bsum[blockIdx.x] = sm[1023];
}
__global__ void k_scan2(int NB) {
    __shared__ int sm[128];
    int t = threadIdx.x;
    sm[t] = (t < NB) ? g_bsum[t] : 0;
    __syncthreads();
    #pragma unroll
    for (int off = 1; off < 128; off <<= 1) {
        int v = (t >= off) ? sm[t - off] : 0;
        __syncthreads();
        sm[t] += v;
        __syncthreads();
    }
    if (t < NB) g_bsum[t] = sm[t];   // inclusive per-block totals
}
__global__ void k_scan3(int N, int E) {
    int i = blockIdx.x * blockDim.x + threadIdx.x;
    if (i > N) return;
    if (i == N) { g_off[N] = E; return; }
    int blk = i >> 10;
    int base = blk ? g_bsum[blk - 1] : 0;
    int d = g_deg[i];
    int off = base + g_scanI[i] - d;   // exclusive
    g_off[i] = off;
    g_pos[i] = off;
    g_dinv[i] = rsqrtf((float)(d + 1));
}

// ---------------- CSR fill ----------------
__global__ void k_fill(const void* __restrict__ ei, int E) {
    int e = blockIdx.x * blockDim.x + threadIdx.x;
    if (e >= E) return;
    int s, d2;
    if (g_eflag) { const int* p = (const int*)ei; s = p[e]; d2 = p[E + e]; }
    else { const long long* p = (const long long*)ei; s = (int)p[e]; d2 = (int)p[E + e]; }
    int pos = atomicAdd(&g_pos[d2], 1);
    g_csr[pos] = s;
}

// ---------------- gather (MLP=4) fused with LN2 ----------------
__global__ void k_gather_ln2(const float* __restrict__ x,
                             const float* __restrict__ bconv,
                             const float* __restrict__ g, const float* __restrict__ b,
                             float* __restrict__ out, int N) {
    int row = blockIdx.x * (blockDim.x >> 5) + (threadIdx.x >> 5);
    if (row >= N) return;
    int lane = threadIdx.x & 31;
    float4 acc = ((const float4*)g_HW)[row * 32 + lane];   // self term (scaled)
    int e = g_off[row], e1 = g_off[row + 1];
    for (; e + 4 <= e1; e += 4) {
        int s0 = g_csr[e], s1 = g_csr[e + 1], s2 = g_csr[e + 2], s3 = g_csr[e + 3];
        float4 v0 = ((const float4*)g_HW)[s0 * 32 + lane];
        float4 v1 = ((const float4*)g_HW)[s1 * 32 + lane];
        float4 v2 = ((const float4*)g_HW)[s2 * 32 + lane];
        float4 v3 = ((const float4*)g_HW)[s3 * 32 + lane];
        acc.x += (v0.x + v1.x) + (v2.x + v3.x);
        acc.y += (v0.y + v1.y) + (v2.y + v3.y);
        acc.z += (v0.z + v1.z) + (v2.z + v3.z);
        acc.w += (v0.w + v1.w) + (v2.w + v3.w);
    }
    for (; e < e1; e++) {
        int s = g_csr[e];
        float4 v = ((const float4*)g_HW)[s * 32 + lane];
        acc.x += v.x; acc.y += v.y; acc.z += v.z; acc.w += v.w;
    }
    float di = g_dinv[row];
    float4 xv  = ((const float4*)x)[row * 32 + lane];
    float4 bcv = ((const float4*)bconv)[lane];
    float4 v;
    v.x = xv.x + acc.x * di + bcv.x;
    v.y = xv.y + acc.y * di + bcv.y;
    v.z = xv.z + acc.z * di + bcv.z;
    v.w = xv.w + acc.w * di + bcv.w;
    float s  = v.x + v.y + v.z + v.w;
    float ss = v.x*v.x + v.y*v.y + v.z*v.z + v.w*v.w;
    #pragma unroll
    for (int o = 16; o; o >>= 1) {
        s  += __shfl_xor_sync(0xffffffffu, s,  o);
        ss += __shfl_xor_sync(0xffffffffu, ss, o);
    }
    float mu  = s * (1.0f / D);
    float var = ss * (1.0f / D) - mu * mu;
    float rs  = rsqrtf(var + 1e-5f);
    float4 gg = ((const float4*)g)[lane];
    float4 bb = ((const float4*)b)[lane];
    float4 r;
    r.x = (v.x - mu) * rs * gg.x + bb.x;
    r.y = (v.y - mu) * rs * gg.y + bb.y;
    r.z = (v.z - mu) * rs * gg.z + bb.z;
    r.w = (v.w - mu) * rs * gg.w + bb.w;
    ((float4*)(out + (size_t)row * D))[lane] = r;
}

// ---------------- tf32 mma.sync GEMM, double-buffered staging -------------
#define KCH 64
#define APITCH 68
#define WPITCH 136
#define ABUF (128 * APITCH)
#define WBUF (KCH * WPITCH)
#define GEMM_SMEM ((2 * (ABUF + WBUF)) * (int)sizeof(float))

__global__ void __launch_bounds__(256, 1) k_gemm_tc(
    const float* __restrict__ A, const float* __restrict__ W,
    const float* __restrict__ bias, const float* __restrict__ res,
    const float* __restrict__ dinv,
    float* __restrict__ out, int N, int K, int ncols, int mode)
{
    extern __shared__ float sm[];
    int tid = threadIdx.x, wid = tid >> 5, lane = tid & 31;
    int rowBase = blockIdx.x * 128, colBase = blockIdx.y * 128;
    int wm = (wid & 3) * 32;
    int wn = (wid >> 2) * 64;
    int lq = lane >> 2, lr = lane & 3;

    float4 aR[8], wR[8];
    int aRow[8];
    #pragma unroll
    for (int i = 0; i < 8; i++) aRow[i] = rowBase + ((tid + i * 256) >> 4);

    auto load_regs = [&](int kc) {
        #pragma unroll
        for (int i = 0; i < 8; i++) {
            int idx = tid + i * 256;
            int k4 = (idx & 15) << 2;
            aR[i] = (aRow[i] < N)
                  ? *(const float4*)&A[(size_t)aRow[i] * K + kc + k4]
                  : make_float4(0.f, 0.f, 0.f, 0.f);
        }
        #pragma unroll
        for (int i = 0; i < 8; i++) {
            int idx = tid + i * 256;
            int rr = idx >> 5, n4 = (idx & 31) << 2;
            wR[i] = *(const float4*)&W[(size_t)(kc + rr) * ncols + colBase + n4];
        }
    };
    auto store_smem = [&](int buf) {
        float* As = sm + buf * ABUF;
        float* Ws = sm + 2 * ABUF + buf * WBUF;
        #pragma unroll
        for (int i = 0; i < 8; i++) {
            int idx = tid + i * 256;
            int r = idx >> 4, k4 = (idx & 15) << 2;
            uint4 t;
            t.x = tf32_bits(aR[i].x); t.y = tf32_bits(aR[i].y);
            t.z = tf32_bits(aR[i].z); t.w = tf32_bits(aR[i].w);
            *(uint4*)&As[r * APITCH + k4] = t;
        }
        #pragma unroll
        for (int i = 0; i < 8; i++) {
            int idx = tid + i * 256;
            int rr = idx >> 5, n4 = (idx & 31) << 2;
            uint4 t;
            t.x = tf32_bits(wR[i].x); t.y = tf32_bits(wR[i].y);
            t.z = tf32_bits(wR[i].z); t.w = tf32_bits(wR[i].w);
            *(uint4*)&Ws[rr * WPITCH + n4] = t;
        }
    };

    float acc[2][8][4];
    #pragma unroll
    for (int i = 0; i < 2; i++)
        #pragma unroll
        for (int j = 0; j < 8; j++)
            #pragma unroll
            for (int k = 0; k < 4; k++) acc[i][j][k] = 0.0f;

    int nch = K / KCH;
    load_regs(0);
    store_smem(0);
    for (int ch = 0; ch < nch; ch++) {
        __syncthreads();
        if (ch + 1 < nch) load_regs((ch + 1) * KCH);
        const float* As = sm + (ch & 1) * ABUF;
        const float* Ws = sm + 2 * ABUF + (ch & 1) * WBUF;
        #pragma unroll
        for (int ks = 0; ks < KCH; ks += 8) {
            uint32_t a[2][4], b[8][2];
            #pragma unroll
            for (int mf = 0; mf < 2; mf++) {
                int r0 = wm + mf * 16 + lq;
                a[mf][0] = __float_as_uint(As[r0 * APITCH + ks + lr]);
                a[mf][1] = __float_as_uint(As[(r0 + 8) * APITCH + ks + lr]);
                a[mf][2] = __float_as_uint(As[r0 * APITCH + ks + lr + 4]);
                a[mf][3] = __float_as_uint(As[(r0 + 8) * APITCH + ks + lr + 4]);
            }
            #pragma unroll
            for (int nf = 0; nf < 8; nf++) {
                int c0 = wn + nf * 8 + lq;
                b[nf][0] = __float_as_uint(Ws[(ks + lr) * WPITCH + c0]);
                b[nf][1] = __float_as_uint(Ws[(ks + lr + 4) * WPITCH + c0]);
            }
            #pragma unroll
            for (int mf = 0; mf < 2; mf++)
                #pragma unroll
                for (int nf = 0; nf < 8; nf++) {
                    asm volatile(
                        "mma.sync.aligned.m16n8k8.row.col.f32.tf32.tf32.f32 "
                        "{%0,%1,%2,%3}, {%4,%5,%6,%7}, {%8,%9}, {%0,%1,%2,%3};"
                        : "+f"(acc[mf][nf][0]), "+f"(acc[mf][nf][1]),
                          "+f"(acc[mf][nf][2]), "+f"(acc[mf][nf][3])
                        : "r"(a[mf][0]), "r"(a[mf][1]), "r"(a[mf][2]), "r"(a[mf][3]),
                          "r"(b[nf][0]), "r"(b[nf][1]));
                }
        }
        if (ch + 1 < nch) store_smem((ch + 1) & 1);
    }

    #pragma unroll
    for (int mf = 0; mf < 2; mf++) {
        int r0 = rowBase + wm + mf * 16 + lq;
        #pragma unroll
        for (int half = 0; half < 2; half++) {
            int row = r0 + half * 8;
            if (row >= N) continue;
            float di = (mode == 3) ? dinv[row] : 1.0f;
            #pragma unroll
            for (int nf = 0; nf < 8; nf++) {
                int col = colBase + wn + nf * 8 + lr * 2;
                float v0 = acc[mf][nf][half * 2];
                float v1 = acc[mf][nf][half * 2 + 1];
                if (mode == 1 || mode == 2) {
                    v0 = gelu_f(v0 + bias[col]);
                    v1 = gelu_f(v1 + bias[col + 1]);
                }
                if (mode == 2) {
                    float2 r2 = *(const float2*)&res[(size_t)row * ncols + col];
                    v0 += r2.x; v1 += r2.y;
                }
                if (mode == 3) { v0 *= di; v1 *= di; }
                *(float2*)&out[(size_t)row * ncols + col] = make_float2(v0, v1);
            }
        }
    }
}

// ---------------- launch ----------------
extern "C" void kernel_launch(void* const* d_in, const int* in_sizes, int n_in,
                              void* d_out, int out_size) {
    const float* x    = (const float*)d_in[0];
    const void*  ei   = d_in[1];
    const float* ln1g = (const float*)d_in[3];
    const float* ln1b = (const float*)d_in[4];
    const float* Wc   = (const float*)d_in[5];
    const float* bc   = (const float*)d_in[6];
    const float* ln2g = (const float*)d_in[7];
    const float* ln2b = (const float*)d_in[8];
    const float* W1   = (const float*)d_in[9];
    const float* b1   = (const float*)d_in[10];
    const float* W2   = (const float*)d_in[11];
    const float* b2   = (const float*)d_in[12];
    float* out = (float*)d_out;

    int N = in_sizes[0] / D;
    int E = in_sizes[1] / 2;

    static int attr_set = 0;
    if (!attr_set) {
        cudaFuncSetAttribute(k_gemm_tc, cudaFuncAttributeMaxDynamicSharedMemorySize, GEMM_SMEM);
        attr_set = 1;
    }

    float* gH;    cudaGetSymbolAddress((void**)&gH,    g_H);
    float* gHW;   cudaGetSymbolAddress((void**)&gHW,   g_HW);
    float* gF1;   cudaGetSymbolAddress((void**)&gF1,   g_F1);
    float* gdinv; cudaGetSymbolAddress((void**)&gdinv, g_dinv);

    dim3 lnBlk(32, 8);
    int lnGrid = (N + 7) / 8;
    int rowBlocks = (N + 127) / 128;
    int NB = (N + 1023) / 1024;

    // 0. edge dtype detection
    k_detect<<<1, 256>>>((const unsigned long long*)ei, (long long)E,
                         (unsigned long long)N);
    // 1-6. CSR build: histogram -> 3-phase scan -> fill
    k_deginit<<<(N + 255) / 256, 256>>>(N);
    k_degcount<<<(E + 255) / 256, 256>>>(ei, E);
    k_scan1<<<NB, 1024>>>(N);
    k_scan2<<<1, 128>>>(NB);
    k_scan3<<<(N + 256) / 256, 256>>>(N, E);
    k_fill<<<(E + 255) / 256, 256>>>(ei, E);
    // 7. H = gelu(LN1(x))
    k_rowln1<<<lnGrid, lnBlk>>>(x, ln1g, ln1b, gH, N);
    // 8. HWs = (H @ W_conv) * dinv[row]
    k_gemm_tc<<<dim3(rowBlocks, 1), 256, GEMM_SMEM>>>(
        gH, Wc, nullptr, nullptr, gdinv, gHW, N, D, D, 3);
    // 9. H = LN2(x + agg + b_conv)   [gather, MLP=4]
    {
        int wpb = 8;
        int blocks = (N + wpb - 1) / wpb;
        k_gather_ln2<<<blocks, wpb * 32>>>(x, bc, ln2g, ln2b, gH, N);
    }
    // 10. F1 = gelu(H @ W1 + b1)
    k_gemm_tc<<<dim3(rowBlocks, 4), 256, GEMM_SMEM>>>(
        gH, W1, b1, nullptr, nullptr, gF1, N, D, D4, 1);
    // 11. out = x + gelu(F1 @ W2 + b2)
    k_gemm_tc<<<dim3(rowBlocks, 1), 256, GEMM_SMEM>>>(
        gF1, W2, b2, x, nullptr, out, N, D4, D, 2);
}

// round 7
// speedup vs baseline: 2.0291x; 1.2193x over previous
#include <cuda_runtime.h>
#include <math.h>
#include <stdint.h>

#define D    128
#define D4   512
#define MAXN 100000
#define MAXE 1000000

// ---------------- scratch (no allocations allowed) ----------------
__device__ float g_H  [MAXN * D];    // gelu(LN1(x)), later LN2(conv)
__device__ float g_HW [MAXN * D];    // h @ W_conv (raw)
__device__ float g_F1 [MAXN * D4];   // FFN hidden
__device__ int   g_deg [MAXN];
__device__ int   g_scanI[MAXN];
__device__ int   g_bsum[128];
__device__ int   g_off [MAXN + 1];
__device__ int   g_pos [MAXN];
__device__ int   g_csr [MAXE];
__device__ float g_dinv[MAXN];
__device__ int   g_eflag;            // 1 => edge_index stored as int32

__device__ __forceinline__ float gelu_f(float x) {
    return 0.5f * x * (1.0f + erff(x * 0.70710678118654752f));
}
__device__ __forceinline__ uint32_t tf32_bits(float x) {
    uint32_t r;
    asm("cvt.rna.tf32.f32 %0, %1;" : "=r"(r) : "f"(x));
    return r;
}
__device__ __forceinline__ uint32_t smem_u32(const void* p) {
    uint32_t a;
    asm("{ .reg .u64 t; cvta.to.shared.u64 t, %1; cvt.u32.u64 %0, t; }"
        : "=r"(a) : "l"(p));
    return a;
}

// ---------------- detect edge dtype + zero degree (merged) ----------------
__global__ void k_detect_init(const unsigned long long* __restrict__ p, long long E,
                              unsigned long long NN, int N) {
    int i = blockIdx.x * blockDim.x + threadIdx.x;
    if (i < N) g_deg[i] = 0;
    if (blockIdx.x == 0) {
        __shared__ int bad;
        if (threadIdx.x == 0) bad = 0;
        __syncthreads();
        long long step = E / (long long)blockDim.x;
        if (step < 1) step = 1;
        long long idx = (long long)threadIdx.x * step;
        if (idx < E && p[idx] >= NN) bad = 1;
        __syncthreads();
        if (threadIdx.x == 0) g_eflag = bad;
    }
}

// ---------------- LN1 + gelu ----------------
__global__ void k_rowln1(const float* __restrict__ x,
                         const float* __restrict__ g, const float* __restrict__ b,
                         float* __restrict__ out, int N) {
    int row = blockIdx.x * blockDim.y + threadIdx.y;
    if (row >= N) return;
    int l = threadIdx.x;
    float4 v = ((const float4*)(x + (size_t)row * D))[l];
    float s  = v.x + v.y + v.z + v.w;
    float ss = v.x*v.x + v.y*v.y + v.z*v.z + v.w*v.w;
    #pragma unroll
    for (int o = 16; o; o >>= 1) {
        s  += __shfl_xor_sync(0xffffffffu, s,  o);
        ss += __shfl_xor_sync(0xffffffffu, ss, o);
    }
    float mu  = s * (1.0f / D);
    float var = ss * (1.0f / D) - mu * mu;
    float rs  = rsqrtf(var + 1e-5f);
    float4 gg = ((const float4*)g)[l];
    float4 bb = ((const float4*)b)[l];
    float4 r;
    r.x = gelu_f((v.x - mu) * rs * gg.x + bb.x);
    r.y = gelu_f((v.y - mu) * rs * gg.y + bb.y);
    r.z = gelu_f((v.z - mu) * rs * gg.z + bb.z);
    r.w = gelu_f((v.w - mu) * rs * gg.w + bb.w);
    ((float4*)(out + (size_t)row * D))[l] = r;
}

// ---------------- degree histogram ----------------
__global__ void k_degcount(const void* __restrict__ ei, int E) {
    int e = blockIdx.x * blockDim.x + threadIdx.x;
    if (e >= E) return;
    int dst;
    if (g_eflag) dst = ((const int*)ei)[E + e];
    else         dst = (int)((const long long*)ei)[E + e];
    atomicAdd(&g_deg[dst], 1);
}

// ---------------- parallel 3-phase scan ----------------
__global__ void k_scan1(int N) {
    __shared__ int sm[1024];
    int i = blockIdx.x * 1024 + threadIdx.x;
    int v = (i < N) ? g_deg[i] : 0;
    sm[threadIdx.x] = v;
    __syncthreads();
    #pragma unroll
    for (int off = 1; off < 1024; off <<= 1) {
        int t = (threadIdx.x >= off) ? sm[threadIdx.x - off] : 0;
        __syncthreads();
        sm[threadIdx.x] += t;
        __syncthreads();
    }
    if (i < N) g_scanI[i] = sm[threadIdx.x];
    if (threadIdx.x == 1023) g_bsum[blockIdx.x] = sm[1023];
}
__global__ void k_scan2(int NB) {
    __shared__ int sm[128];
    int t = threadIdx.x;
    sm[t] = (t < NB) ? g_bsum[t] : 0;
    __syncthreads();
    #pragma unroll
    for (int off = 1; off < 128; off <<= 1) {
        int v = (t >= off) ? sm[t - off] : 0;
        __syncthreads();
        sm[t] += v;
        __syncthreads();
    }
    if (t < NB) g_bsum[t] = sm[t];
}
__global__ void k_scan3(int N, int E) {
    int i = blockIdx.x * blockDim.x + threadIdx.x;
    if (i > N) return;
    if (i == N) { g_off[N] = E; return; }
    int blk = i >> 10;
    int base = blk ? g_bsum[blk - 1] : 0;
    int d = g_deg[i];
    int off = base + g_scanI[i] - d;
    g_off[i] = off;
    g_pos[i] = off;
    g_dinv[i] = rsqrtf((float)(d + 1));
}

// ---------------- CSR fill ----------------
__global__ void k_fill(const void* __restrict__ ei, int E) {
    int e = blockIdx.x * blockDim.x + threadIdx.x;
    if (e >= E) return;
    int s, d2;
    if (g_eflag) { const int* p = (const int*)ei; s = p[e]; d2 = p[E + e]; }
    else { const long long* p = (const long long*)ei; s = (int)p[e]; d2 = (int)p[E + e]; }
    int pos = atomicAdd(&g_pos[d2], 1);
    g_csr[pos] = s;
}

// ---------------- gather (MLP=4, dinv per src) fused with LN2 ----------------
__global__ void k_gather_ln2(const float* __restrict__ x,
                             const float* __restrict__ bconv,
                             const float* __restrict__ g, const float* __restrict__ b,
                             float* __restrict__ out, int N) {
    int row = blockIdx.x * (blockDim.x >> 5) + (threadIdx.x >> 5);
    if (row >= N) return;
    int lane = threadIdx.x & 31;
    float di = g_dinv[row];
    float4 acc = ((const float4*)g_HW)[row * 32 + lane];   // self term
    acc.x *= di; acc.y *= di; acc.z *= di; acc.w *= di;
    int e = g_off[row], e1 = g_off[row + 1];
    for (; e + 4 <= e1; e += 4) {
        int s0 = g_csr[e], s1 = g_csr[e + 1], s2 = g_csr[e + 2], s3 = g_csr[e + 3];
        float c0 = g_dinv[s0], c1 = g_dinv[s1], c2 = g_dinv[s2], c3 = g_dinv[s3];
        float4 v0 = ((const float4*)g_HW)[s0 * 32 + lane];
        float4 v1 = ((const float4*)g_HW)[s1 * 32 + lane];
        float4 v2 = ((const float4*)g_HW)[s2 * 32 + lane];
        float4 v3 = ((const float4*)g_HW)[s3 * 32 + lane];
        acc.x += (v0.x*c0 + v1.x*c1) + (v2.x*c2 + v3.x*c3);
        acc.y += (v0.y*c0 + v1.y*c1) + (v2.y*c2 + v3.y*c3);
        acc.z += (v0.z*c0 + v1.z*c1) + (v2.z*c2 + v3.z*c3);
        acc.w += (v0.w*c0 + v1.w*c1) + (v2.w*c2 + v3.w*c3);
    }
    for (; e < e1; e++) {
        int s = g_csr[e];
        float c = g_dinv[s];
        float4 v = ((const float4*)g_HW)[s * 32 + lane];
        acc.x += v.x*c; acc.y += v.y*c; acc.z += v.z*c; acc.w += v.w*c;
    }
    float4 xv  = ((const float4*)x)[row * 32 + lane];
    float4 bcv = ((const float4*)bconv)[lane];
    float4 v;
    v.x = xv.x + acc.x * di + bcv.x;
    v.y = xv.y + acc.y * di + bcv.y;
    v.z = xv.z + acc.z * di + bcv.z;
    v.w = xv.w + acc.w * di + bcv.w;
    float s  = v.x + v.y + v.z + v.w;
    float ss = v.x*v.x + v.y*v.y + v.z*v.z + v.w*v.w;
    #pragma unroll
    for (int o = 16; o; o >>= 1) {
        s  += __shfl_xor_sync(0xffffffffu, s,  o);
        ss += __shfl_xor_sync(0xffffffffu, ss, o);
    }
    float mu  = s * (1.0f / D);
    float var = ss * (1.0f / D) - mu * mu;
    float rs  = rsqrtf(var + 1e-5f);
    float4 gg = ((const float4*)g)[lane];
    float4 bb = ((const float4*)b)[lane];
    float4 r;
    r.x = (v.x - mu) * rs * gg.x + bb.x;
    r.y = (v.y - mu) * rs * gg.y + bb.y;
    r.z = (v.z - mu) * rs * gg.z + bb.z;
    r.w = (v.w - mu) * rs * gg.w + bb.w;
    ((float4*)(out + (size_t)row * D))[lane] = r;
}

// ---------------- tf32 mma.sync GEMM, cp.async double-buffer, 2 CTA/SM -----
// CTA 256 thr -> 128x128 tile; warps 4(m)x2(n), warp tile 32x64; KCH=32.
// smem holds raw fp32; cvt to tf32 at fragment load.
// mode 0: raw. 1: gelu(acc+bias). 2: res + gelu(acc+bias).
#define KCH 32
#define APITCH 36
#define WPITCH 136
#define ABUF (128 * APITCH)
#define WBUF (KCH * WPITCH)
#define GEMM_SMEM ((2 * (ABUF + WBUF)) * (int)sizeof(float))

__global__ void __launch_bounds__(256, 2) k_gemm_tc(
    const float* __restrict__ A, const float* __restrict__ W,
    const float* __restrict__ bias, const float* __restrict__ res,
    float* __restrict__ out, int N, int K, int ncols, int mode)
{
    extern __shared__ float sm[];
    uint32_t smb = smem_u32(sm);
    int tid = threadIdx.x, wid = tid >> 5, lane = tid & 31;
    int rowBase = blockIdx.x * 128, colBase = blockIdx.y * 128;
    int wm = (wid & 3) * 32;
    int wn = (wid >> 2) * 64;
    int lq = lane >> 2, lr = lane & 3;

    auto issue = [&](int ch) {
        int kc = ch * KCH;
        int buf = ch & 1;
        uint32_t asb = smb + (uint32_t)(buf * ABUF) * 4u;
        uint32_t wsb = smb + (uint32_t)(2 * ABUF + buf * WBUF) * 4u;
        #pragma unroll
        for (int i = 0; i < 4; i++) {
            int c = tid + i * 256;            // A: 1024 chunks of 16B
            int r = c >> 3, kp = (c & 7) << 2;
            int gr = rowBase + r;
            const float* src = &A[(size_t)gr * K + kc + kp];
            uint32_t dst = asb + (uint32_t)(r * APITCH + kp) * 4u;
            int sz = (gr < N) ? 16 : 0;
            asm volatile("cp.async.ca.shared.global [%0], [%1], 16, %2;"
                         :: "r"(dst), "l"(src), "r"(sz));
        }
        #pragma unroll
        for (int i = 0; i < 4; i++) {
            int c = tid + i * 256;            // W: 1024 chunks of 16B
            int rr = c >> 5, np = (c & 31) << 2;
            const float* src = &W[(size_t)(kc + rr) * ncols + colBase + np];
            uint32_t dst = wsb + (uint32_t)(rr * WPITCH + np) * 4u;
            asm volatile("cp.async.ca.shared.global [%0], [%1], 16;"
                         :: "r"(dst), "l"(src));
        }
        asm volatile("cp.async.commit_group;");
    };

    float acc[2][8][4];
    #pragma unroll
    for (int i = 0; i < 2; i++)
        #pragma unroll
        for (int j = 0; j < 8; j++)
            #pragma unroll
            for (int k = 0; k < 4; k++) acc[i][j][k] = 0.0f;

    int nch = K / KCH;
    issue(0);
    for (int ch = 0; ch < nch; ch++) {
        if (ch + 1 < nch) {
            issue(ch + 1);
            asm volatile("cp.async.wait_group 1;");
        } else {
            asm volatile("cp.async.wait_group 0;");
        }
        __syncthreads();
        const float* As = sm + (ch & 1) * ABUF;
        const float* Ws = sm + 2 * ABUF + (ch & 1) * WBUF;
        #pragma unroll
        for (int ks = 0; ks < KCH; ks += 8) {
            uint32_t a[2][4], b[8][2];
            #pragma unroll
            for (int mf = 0; mf < 2; mf++) {
                int r0 = wm + mf * 16 + lq;
                a[mf][0] = tf32_bits(As[r0 * APITCH + ks + lr]);
                a[mf][1] = tf32_bits(As[(r0 + 8) * APITCH + ks + lr]);
                a[mf][2] = tf32_bits(As[r0 * APITCH + ks + lr + 4]);
                a[mf][3] = tf32_bits(As[(r0 + 8) * APITCH + ks + lr + 4]);
            }
            #pragma unroll
            for (int nf = 0; nf < 8; nf++) {
                int c0 = wn + nf * 8 + lq;
                b[nf][0] = tf32_bits(Ws[(ks + lr) * WPITCH + c0]);
                b[nf][1] = tf32_bits(Ws[(ks + lr + 4) * WPITCH + c0]);
            }
            #pragma unroll
            for (int mf = 0; mf < 2; mf++)
                #pragma unroll
                for (int nf = 0; nf < 8; nf++) {
                    asm volatile(
                        "mma.sync.aligned.m16n8k8.row.col.f32.tf32.tf32.f32 "
                        "{%0,%1,%2,%3}, {%4,%5,%6,%7}, {%8,%9}, {%0,%1,%2,%3};"
                        : "+f"(acc[mf][nf][0]), "+f"(acc[mf][nf][1]),
                          "+f"(acc[mf][nf][2]), "+f"(acc[mf][nf][3])
                        : "r"(a[mf][0]), "r"(a[mf][1]), "r"(a[mf][2]), "r"(a[mf][3]),
                          "r"(b[nf][0]), "r"(b[nf][1]));
                }
        }
        __syncthreads();
    }

    #pragma unroll
    for (int mf = 0; mf < 2; mf++) {
        int r0 = rowBase + wm + mf * 16 + lq;
        #pragma unroll
        for (int half = 0; half < 2; half++) {
            int row = r0 + half * 8;
            if (row >= N) continue;
            #pragma unroll
            for (int nf = 0; nf < 8; nf++) {
                int col = colBase + wn + nf * 8 + lr * 2;
                float v0 = acc[mf][nf][half * 2];
                float v1 = acc[mf][nf][half * 2 + 1];
                if (mode >= 1) {
                    v0 = gelu_f(v0 + bias[col]);
                    v1 = gelu_f(v1 + bias[col + 1]);
                }
                if (mode == 2) {
                    float2 r2 = *(const float2*)&res[(size_t)row * ncols + col];
                    v0 += r2.x; v1 += r2.y;
                }
                *(float2*)&out[(size_t)row * ncols + col] = make_float2(v0, v1);
            }
        }
    }
}

// ---------------- launch ----------------
extern "C" void kernel_launch(void* const* d_in, const int* in_sizes, int n_in,
                              void* d_out, int out_size) {
    const float* x    = (const float*)d_in[0];
    const void*  ei   = d_in[1];
    const float* ln1g = (const float*)d_in[3];
    const float* ln1b = (const float*)d_in[4];
    const float* Wc   = (const float*)d_in[5];
    const float* bc   = (const float*)d_in[6];
    const float* ln2g = (const float*)d_in[7];
    const float* ln2b = (const float*)d_in[8];
    const float* W1   = (const float*)d_in[9];
    const float* b1   = (const float*)d_in[10];
    const float* W2   = (const float*)d_in[11];
    const float* b2   = (const float*)d_in[12];
    float* out = (float*)d_out;

    int N = in_sizes[0] / D;
    int E = in_sizes[1] / 2;

    static int attr_set = 0;
    if (!attr_set) {
        cudaFuncSetAttribute(k_gemm_tc, cudaFuncAttributeMaxDynamicSharedMemorySize, GEMM_SMEM);
        attr_set = 1;
    }

    float* gH;    cudaGetSymbolAddress((void**)&gH,    g_H);
    float* gHW;   cudaGetSymbolAddress((void**)&gHW,   g_HW);
    float* gF1;   cudaGetSymbolAddress((void**)&gF1,   g_F1);

    dim3 lnBlk(32, 8);
    int lnGrid = (N + 7) / 8;
    int rowBlocks = (N + 127) / 128;
    int NB = (N + 1023) / 1024;

    // 0. detect + zero degrees
    k_detect_init<<<(N + 255) / 256, 256>>>((const unsigned long long*)ei,
                                            (long long)E, (unsigned long long)N, N);
    // 1. H = gelu(LN1(x))
    k_rowln1<<<lnGrid, lnBlk>>>(x, ln1g, ln1b, gH, N);
    // 2. degree histogram
    k_degcount<<<(E + 255) / 256, 256>>>(ei, E);
    // 3. HW = H @ W_conv    <-- PROFILED LAUNCH (index 3)
    k_gemm_tc<<<dim3(rowBlocks, 1), 256, GEMM_SMEM>>>(
        gH, Wc, nullptr, nullptr, gHW, N, D, D, 0);
    // 4-7. scan chain + CSR fill
    k_scan1<<<NB, 1024>>>(N);
    k_scan2<<<1, 128>>>(NB);
    k_scan3<<<(N + 256) / 256, 256>>>(N, E);
    k_fill<<<(E + 255) / 256, 256>>>(ei, E);
    // 8. H = LN2(x + agg + b_conv)
    {
        int wpb = 8;
        int blocks = (N + wpb - 1) / wpb;
        k_gather_ln2<<<blocks, wpb * 32>>>(x, bc, ln2g, ln2b, gH, N);
    }
    // 9. F1 = gelu(H @ W1 + b1)
    k_gemm_tc<<<dim3(rowBlocks, 4), 256, GEMM_SMEM>>>(
        gH, W1, b1, nullptr, gF1, N, D, D4, 1);
    // 10. out = x + gelu(F1 @ W2 + b2)
    k_gemm_tc<<<dim3(rowBlocks, 1), 256, GEMM_SMEM>>>(
        gF1, W2, b2, x, out, N, D4, D, 2);
}

// round 8
// speedup vs baseline: 2.1370x; 1.0532x over previous
#include <cuda_runtime.h>
#include <math.h>
#include <stdint.h>

#define D    128
#define D4   512
#define MAXN 100000
#define MAXE 1000000

// ---------------- scratch (no allocations allowed) ----------------
__device__ float g_H  [MAXN * D];    // gelu(LN1(x)), later LN2(conv)
__device__ float g_HW [MAXN * D];    // h @ W_conv (raw)
__device__ float g_F1 [MAXN * D4];   // FFN hidden
__device__ int   g_deg [MAXN];
__device__ int   g_scanI[MAXN];
__device__ int   g_bsum[128];
__device__ int   g_off [MAXN + 1];
__device__ int   g_pos [MAXN];
__device__ int   g_csr [MAXE];
__device__ float g_dinv[MAXN];
__device__ int   g_eflag;            // 1 => edge_index stored as int32

__device__ __forceinline__ float gelu_f(float x) {
    return 0.5f * x * (1.0f + erff(x * 0.70710678118654752f));
}
__device__ __forceinline__ uint32_t smem_u32(const void* p) {
    uint32_t a;
    asm("{ .reg .u64 t; cvta.to.shared.u64 t, %1; cvt.u32.u64 %0, t; }"
        : "=r"(a) : "l"(p));
    return a;
}

// ---------------- detect edge dtype + zero degree (merged) ----------------
__global__ void k_detect_init(const unsigned long long* __restrict__ p, long long E,
                              unsigned long long NN, int N) {
    int i = blockIdx.x * blockDim.x + threadIdx.x;
    if (i < N) g_deg[i] = 0;
    if (blockIdx.x == 0) {
        __shared__ int bad;
        if (threadIdx.x == 0) bad = 0;
        __syncthreads();
        long long step = E / (long long)blockDim.x;
        if (step < 1) step = 1;
        long long idx = (long long)threadIdx.x * step;
        if (idx < E && p[idx] >= NN) bad = 1;
        __syncthreads();
        if (threadIdx.x == 0) g_eflag = bad;
    }
}

// ---------------- LN1 + gelu ----------------
__global__ void k_rowln1(const float* __restrict__ x,
                         const float* __restrict__ g, const float* __restrict__ b,
                         float* __restrict__ out, int N) {
    int row = blockIdx.x * blockDim.y + threadIdx.y;
    if (row >= N) return;
    int l = threadIdx.x;
    float4 v = ((const float4*)(x + (size_t)row * D))[l];
    float s  = v.x + v.y + v.z + v.w;
    float ss = v.x*v.x + v.y*v.y + v.z*v.z + v.w*v.w;
    #pragma unroll
    for (int o = 16; o; o >>= 1) {
        s  += __shfl_xor_sync(0xffffffffu, s,  o);
        ss += __shfl_xor_sync(0xffffffffu, ss, o);
    }
    float mu  = s * (1.0f / D);
    float var = ss * (1.0f / D) - mu * mu;
    float rs  = rsqrtf(var + 1e-5f);
    float4 gg = ((const float4*)g)[l];
    float4 bb = ((const float4*)b)[l];
    float4 r;
    r.x = gelu_f((v.x - mu) * rs * gg.x + bb.x);
    r.y = gelu_f((v.y - mu) * rs * gg.y + bb.y);
    r.z = gelu_f((v.z - mu) * rs * gg.z + bb.z);
    r.w = gelu_f((v.w - mu) * rs * gg.w + bb.w);
    ((float4*)(out + (size_t)row * D))[l] = r;
}

// ---------------- degree histogram ----------------
__global__ void k_degcount(const void* __restrict__ ei, int E) {
    int e = blockIdx.x * blockDim.x + threadIdx.x;
    if (e >= E) return;
    int dst;
    if (g_eflag) dst = ((const int*)ei)[E + e];
    else         dst = (int)((const long long*)ei)[E + e];
    atomicAdd(&g_deg[dst], 1);
}

// ---------------- parallel 3-phase scan ----------------
__global__ void k_scan1(int N) {
    __shared__ int sm[1024];
    int i = blockIdx.x * 1024 + threadIdx.x;
    int v = (i < N) ? g_deg[i] : 0;
    sm[threadIdx.x] = v;
    __syncthreads();
    #pragma unroll
    for (int off = 1; off < 1024; off <<= 1) {
        int t = (threadIdx.x >= off) ? sm[threadIdx.x - off] : 0;
        __syncthreads();
        sm[threadIdx.x] += t;
        __syncthreads();
    }
    if (i < N) g_scanI[i] = sm[threadIdx.x];
    if (threadIdx.x == 1023) g_bsum[blockIdx.x] = sm[1023];
}
__global__ void k_scan2(int NB) {
    __shared__ int sm[128];
    int t = threadIdx.x;
    sm[t] = (t < NB) ? g_bsum[t] : 0;
    __syncthreads();
    #pragma unroll
    for (int off = 1; off < 128; off <<= 1) {
        int v = (t >= off) ? sm[t - off] : 0;
        __syncthreads();
        sm[t] += v;
        __syncthreads();
    }
    if (t < NB) g_bsum[t] = sm[t];
}
__global__ void k_scan3(int N, int E) {
    int i = blockIdx.x * blockDim.x + threadIdx.x;
    if (i > N) return;
    if (i == N) { g_off[N] = E; return; }
    int blk = i >> 10;
    int base = blk ? g_bsum[blk - 1] : 0;
    int d = g_deg[i];
    int off = base + g_scanI[i] - d;
    g_off[i] = off;
    g_pos[i] = off;
    g_dinv[i] = rsqrtf((float)(d + 1));
}

// ---------------- CSR fill ----------------
__global__ void k_fill(const void* __restrict__ ei, int E) {
    int e = blockIdx.x * blockDim.x + threadIdx.x;
    if (e >= E) return;
    int s, d2;
    if (g_eflag) { const int* p = (const int*)ei; s = p[e]; d2 = p[E + e]; }
    else { const long long* p = (const long long*)ei; s = (int)p[e]; d2 = (int)p[E + e]; }
    int pos = atomicAdd(&g_pos[d2], 1);
    g_csr[pos] = s;
}

// ---------------- gather (MLP=4, dinv per src) fused with LN2 ----------------
__global__ void k_gather_ln2(const float* __restrict__ x,
                             const float* __restrict__ bconv,
                             const float* __restrict__ g, const float* __restrict__ b,
                             float* __restrict__ out, int N) {
    int row = blockIdx.x * (blockDim.x >> 5) + (threadIdx.x >> 5);
    if (row >= N) return;
    int lane = threadIdx.x & 31;
    float di = g_dinv[row];
    float4 acc = ((const float4*)g_HW)[row * 32 + lane];   // self term
    acc.x *= di; acc.y *= di; acc.z *= di; acc.w *= di;
    int e = g_off[row], e1 = g_off[row + 1];
    for (; e + 4 <= e1; e += 4) {
        int s0 = g_csr[e], s1 = g_csr[e + 1], s2 = g_csr[e + 2], s3 = g_csr[e + 3];
        float c0 = g_dinv[s0], c1 = g_dinv[s1], c2 = g_dinv[s2], c3 = g_dinv[s3];
        float4 v0 = ((const float4*)g_HW)[s0 * 32 + lane];
        float4 v1 = ((const float4*)g_HW)[s1 * 32 + lane];
        float4 v2 = ((const float4*)g_HW)[s2 * 32 + lane];
        float4 v3 = ((const float4*)g_HW)[s3 * 32 + lane];
        acc.x += (v0.x*c0 + v1.x*c1) + (v2.x*c2 + v3.x*c3);
        acc.y += (v0.y*c0 + v1.y*c1) + (v2.y*c2 + v3.y*c3);
        acc.z += (v0.z*c0 + v1.z*c1) + (v2.z*c2 + v3.z*c3);
        acc.w += (v0.w*c0 + v1.w*c1) + (v2.w*c2 + v3.w*c3);
    }
    for (; e < e1; e++) {
        int s = g_csr[e];
        float c = g_dinv[s];
        float4 v = ((const float4*)g_HW)[s * 32 + lane];
        acc.x += v.x*c; acc.y += v.y*c; acc.z += v.z*c; acc.w += v.w*c;
    }
    float4 xv  = ((const float4*)x)[row * 32 + lane];
    float4 bcv = ((const float4*)bconv)[lane];
    float4 v;
    v.x = xv.x + acc.x * di + bcv.x;
    v.y = xv.y + acc.y * di + bcv.y;
    v.z = xv.z + acc.z * di + bcv.z;
    v.w = xv.w + acc.w * di + bcv.w;
    float s  = v.x + v.y + v.z + v.w;
    float ss = v.x*v.x + v.y*v.y + v.z*v.z + v.w*v.w;
    #pragma unroll
    for (int o = 16; o; o >>= 1) {
        s  += __shfl_xor_sync(0xffffffffu, s,  o);
        ss += __shfl_xor_sync(0xffffffffu, ss, o);
    }
    float mu  = s * (1.0f / D);
    float var = ss * (1.0f / D) - mu * mu;
    float rs  = rsqrtf(var + 1e-5f);
    float4 gg = ((const float4*)g)[lane];
    float4 bb = ((const float4*)b)[lane];
    float4 r;
    r.x = (v.x - mu) * rs * gg.x + bb.x;
    r.y = (v.y - mu) * rs * gg.y + bb.y;
    r.z = (v.z - mu) * rs * gg.z + bb.z;
    r.w = (v.w - mu) * rs * gg.w + bb.w;
    ((float4*)(out + (size_t)row * D))[lane] = r;
}

// ---------------- tf32 mma.sync GEMM, cp.async double-buffer, 2 CTA/SM -----
// CTA 256 thr -> 128x128 tile; warps 4(m)x2(n), warp tile 32x64; KCH=32.
// smem holds raw fp32; raw bits fed to tf32 mma (HW uses upper 19 bits).
// mode 0: raw. 1: gelu(acc+bias). 2: res + gelu(acc+bias).
#define KCH 32
#define APITCH 36
#define WPITCH 136
#define ABUF (128 * APITCH)
#define WBUF (KCH * WPITCH)
#define GEMM_SMEM ((2 * (ABUF + WBUF)) * (int)sizeof(float))

__global__ void __launch_bounds__(256, 2) k_gemm_tc(
    const float* __restrict__ A, const float* __restrict__ W,
    const float* __restrict__ bias, const float* __restrict__ res,
    float* __restrict__ out, int N, int K, int ncols, int mode)
{
    extern __shared__ float sm[];
    uint32_t smb = smem_u32(sm);
    int tid = threadIdx.x, wid = tid >> 5, lane = tid & 31;
    int rowBase = blockIdx.x * 128, colBase = blockIdx.y * 128;
    int wm = (wid & 3) * 32;
    int wn = (wid >> 2) * 64;
    int lq = lane >> 2, lr = lane & 3;

    auto issue = [&](int ch) {
        int kc = ch * KCH;
        int buf = ch & 1;
        uint32_t asb = smb + (uint32_t)(buf * ABUF) * 4u;
        uint32_t wsb = smb + (uint32_t)(2 * ABUF + buf * WBUF) * 4u;
        #pragma unroll
        for (int i = 0; i < 4; i++) {
            int c = tid + i * 256;            // A: 1024 chunks of 16B
            int r = c >> 3, kp = (c & 7) << 2;
            int gr = rowBase + r;
            const float* src = &A[(size_t)gr * K + kc + kp];
            uint32_t dst = asb + (uint32_t)(r * APITCH + kp) * 4u;
            int sz = (gr < N) ? 16 : 0;
            asm volatile("cp.async.ca.shared.global [%0], [%1], 16, %2;"
                         :: "r"(dst), "l"(src), "r"(sz));
        }
        #pragma unroll
        for (int i = 0; i < 4; i++) {
            int c = tid + i * 256;            // W: 1024 chunks of 16B
            int rr = c >> 5, np = (c & 31) << 2;
            const float* src = &W[(size_t)(kc + rr) * ncols + colBase + np];
            uint32_t dst = wsb + (uint32_t)(rr * WPITCH + np) * 4u;
            asm volatile("cp.async.ca.shared.global [%0], [%1], 16;"
                         :: "r"(dst), "l"(src));
        }
        asm volatile("cp.async.commit_group;");
    };

    float acc[2][8][4];
    #pragma unroll
    for (int i = 0; i < 2; i++)
        #pragma unroll
        for (int j = 0; j < 8; j++)
            #pragma unroll
            for (int k = 0; k < 4; k++) acc[i][j][k] = 0.0f;

    int nch = K / KCH;
    issue(0);
    for (int ch = 0; ch < nch; ch++) {
        if (ch + 1 < nch) {
            issue(ch + 1);
            asm volatile("cp.async.wait_group 1;");
        } else {
            asm volatile("cp.async.wait_group 0;");
        }
        __syncthreads();
        const float* As = sm + (ch & 1) * ABUF;
        const float* Ws = sm + 2 * ABUF + (ch & 1) * WBUF;
        #pragma unroll
        for (int ks = 0; ks < KCH; ks += 8) {
            uint32_t a[2][4], b[8][2];
            #pragma unroll
            for (int mf = 0; mf < 2; mf++) {
                int r0 = wm + mf * 16 + lq;
                a[mf][0] = __float_as_uint(As[r0 * APITCH + ks + lr]);
                a[mf][1] = __float_as_uint(As[(r0 + 8) * APITCH + ks + lr]);
                a[mf][2] = __float_as_uint(As[r0 * APITCH + ks + lr + 4]);
                a[mf][3] = __float_as_uint(As[(r0 + 8) * APITCH + ks + lr + 4]);
            }
            #pragma unroll
            for (int nf = 0; nf < 8; nf++) {
                int c0 = wn + nf * 8 + lq;
                b[nf][0] = __float_as_uint(Ws[(ks + lr) * WPITCH + c0]);
                b[nf][1] = __float_as_uint(Ws[(ks + lr + 4) * WPITCH + c0]);
            }
            #pragma unroll
            for (int mf = 0; mf < 2; mf++)
                #pragma unroll
                for (int nf = 0; nf < 8; nf++) {
                    asm volatile(
                        "mma.sync.aligned.m16n8k8.row.col.f32.tf32.tf32.f32 "
                        "{%0,%1,%2,%3}, {%4,%5,%6,%7}, {%8,%9}, {%0,%1,%2,%3};"
                        : "+f"(acc[mf][nf][0]), "+f"(acc[mf][nf][1]),
                          "+f"(acc[mf][nf][2]), "+f"(acc[mf][nf][3])
                        : "r"(a[mf][0]), "r"(a[mf][1]), "r"(a[mf][2]), "r"(a[mf][3]),
                          "r"(b[nf][0]), "r"(b[nf][1]));
                }
        }
        __syncthreads();
    }

    #pragma unroll
    for (int mf = 0; mf < 2; mf++) {
        int r0 = rowBase + wm + mf * 16 + lq;
        #pragma unroll
        for (int half = 0; half < 2; half++) {
            int row = r0 + half * 8;
            if (row >= N) continue;
            #pragma unroll
            for (int nf = 0; nf < 8; nf++) {
                int col = colBase + wn + nf * 8 + lr * 2;
                float v0 = acc[mf][nf][half * 2];
                float v1 = acc[mf][nf][half * 2 + 1];
                if (mode >= 1) {
                    v0 = gelu_f(v0 + bias[col]);
                    v1 = gelu_f(v1 + bias[col + 1]);
                }
                if (mode == 2) {
                    float2 r2 = *(const float2*)&res[(size_t)row * ncols + col];
                    v0 += r2.x; v1 += r2.y;
                }
                *(float2*)&out[(size_t)row * ncols + col] = make_float2(v0, v1);
            }
        }
    }
}

// ---------------- launch ----------------
extern "C" void kernel_launch(void* const* d_in, const int* in_sizes, int n_in,
                              void* d_out, int out_size) {
    const float* x    = (const float*)d_in[0];
    const void*  ei   = d_in[1];
    const float* ln1g = (const float*)d_in[3];
    const float* ln1b = (const float*)d_in[4];
    const float* Wc   = (const float*)d_in[5];
    const float* bc   = (const float*)d_in[6];
    const float* ln2g = (const float*)d_in[7];
    const float* ln2b = (const float*)d_in[8];
    const float* W1   = (const float*)d_in[9];
    const float* b1   = (const float*)d_in[10];
    const float* W2   = (const float*)d_in[11];
    const float* b2   = (const float*)d_in[12];
    float* out = (float*)d_out;

    int N = in_sizes[0] / D;
    int E = in_sizes[1] / 2;

    static int attr_set = 0;
    if (!attr_set) {
        cudaFuncSetAttribute(k_gemm_tc, cudaFuncAttributeMaxDynamicSharedMemorySize, GEMM_SMEM);
        attr_set = 1;
    }

    float* gH;    cudaGetSymbolAddress((void**)&gH,    g_H);
    float* gHW;   cudaGetSymbolAddress((void**)&gHW,   g_HW);
    float* gF1;   cudaGetSymbolAddress((void**)&gF1,   g_F1);

    dim3 lnBlk(32, 8);
    int lnGrid = (N + 7) / 8;
    int rowBlocks = (N + 127) / 128;
    int NB = (N + 1023) / 1024;

    // 0. detect + zero degrees
    k_detect_init<<<(N + 255) / 256, 256>>>((const unsigned long long*)ei,
                                            (long long)E, (unsigned long long)N, N);
    // 1. H = gelu(LN1(x))
    k_rowln1<<<lnGrid, lnBlk>>>(x, ln1g, ln1b, gH, N);
    // 2. degree histogram
    k_degcount<<<(E + 255) / 256, 256>>>(ei, E);
    // 3. HW = H @ W_conv    <-- PROFILED LAUNCH (index 3)
    k_gemm_tc<<<dim3(rowBlocks, 1), 256, GEMM_SMEM>>>(
        gH, Wc, nullptr, nullptr, gHW, N, D, D, 0);
    // 4-7. scan chain + CSR fill
    k_scan1<<<NB, 1024>>>(N);
    k_scan2<<<1, 128>>>(NB);
    k_scan3<<<(N + 256) / 256, 256>>>(N, E);
    k_fill<<<(E + 255) / 256, 256>>>(ei, E);
    // 8. H = LN2(x + agg + b_conv)
    {
        int wpb = 8;
        int blocks = (N + wpb - 1) / wpb;
        k_gather_ln2<<<blocks, wpb * 32>>>(x, bc, ln2g, ln2b, gH, N);
    }
    // 9. F1 = gelu(H @ W1 + b1)
    k_gemm_tc<<<dim3(rowBlocks, 4), 256, GEMM_SMEM>>>(
        gH, W1, b1, nullptr, gF1, N, D, D4, 1);
    // 10. out = x + gelu(F1 @ W2 + b2)
    k_gemm_tc<<<dim3(rowBlocks, 1), 256, GEMM_SMEM>>>(
        gF1, W2, b2, x, out, N, D4, D, 2);
}